// round 5
// baseline (speedup 1.0000x reference)
#include <cuda_runtime.h>
#include <cuda_fp16.h>
#include <cstdint>

// ---------------- problem constants ----------------
#define CIN     2112
#define COUT    192
#define HW      49
#define M_TOTAL 12544          // 256*49
#define BM      64
#define BN      96
#define BK      32
#define CHUNKS  66             // 2112/32
#define NTH     256
#define EPS_BN  1e-5f
#define AST     40             // halfs per A smem row (80B)
#define BST     40             // halfs per B smem row (80B)
#define A_STAGE (BM * AST * 2) // 5120 B
#define B_STAGE (BN * BST * 2) // 7680 B

// ---------------- persistent scratch ----------------
__device__ __half g_wh[COUT * CIN];       // W pre-converted to fp16

__global__ void prep_w_k(const float* __restrict__ W) {
    int i = blockIdx.x * blockDim.x + threadIdx.x;
    if (i < COUT * CIN) g_wh[i] = __float2half_rn(W[i]);
}

// ---------------- helpers ----------------
__device__ __forceinline__ uint32_t smem_u32(const void* p) {
    uint32_t a;
    asm("{ .reg .u64 t; cvta.to.shared.u64 t, %1; cvt.u32.u64 %0, t; }" : "=r"(a) : "l"(p));
    return a;
}
__device__ __forceinline__ void cp16(uint32_t dst, const void* src) {
    asm volatile("cp.async.cg.shared.global [%0], [%1], 16;" :: "r"(dst), "l"(src));
}
__device__ __forceinline__ void ldm_x4(uint32_t* r, uint32_t addr) {
    asm volatile("ldmatrix.sync.aligned.m8n8.x4.shared.b16 {%0,%1,%2,%3}, [%4];"
                 : "=r"(r[0]), "=r"(r[1]), "=r"(r[2]), "=r"(r[3]) : "r"(addr));
}
__device__ __forceinline__ void ldm_x2(uint32_t* r, uint32_t addr) {
    asm volatile("ldmatrix.sync.aligned.m8n8.x2.shared.b16 {%0,%1}, [%2];"
                 : "=r"(r[0]), "=r"(r[1]) : "r"(addr));
}

// ---------------- fused BN+ReLU + fp16 GEMM ----------------
// C[M=12544, N=192] = relu(x*s+t)[M, K=2112] * W[N, K]^T
// grid: 392 CTAs = 196 m-tiles x 2 n-halves
__global__ __launch_bounds__(NTH, 3)
void gemm_k(const float* __restrict__ x,
            const float* __restrict__ gamma, const float* __restrict__ beta,
            const float* __restrict__ mean,  const float* __restrict__ var,
            float* __restrict__ out) {
    __shared__ float2 bns[CIN];                         // 16896 B
    __shared__ __align__(16) __half As[2][BM * AST];    // 10240 B (2 stages)
    __shared__ __align__(16) __half Bs[3][BN * BST];    // 23040 B (3 stages)

    const int tid  = threadIdx.x;
    const int lane = tid & 31, warp = tid >> 5;
    const int wm = warp & 1, wn = warp >> 1;            // 2 x 4 warp grid
    const int g  = lane >> 2, tq = lane & 3;

    const int m0 = (blockIdx.x >> 1) * BM;
    const int n0 = (blockIdx.x & 1) * BN;

    // A loader mapping: thread -> (m = tid&63, 8 consecutive k at kq*8)
    const int am = tid & 63, kq = tid >> 6;
    const int mg = m0 + am;
    const float* xp = x + (size_t)(mg / HW) * ((size_t)CIN * HW) + (mg % HW)
                        + (size_t)(kq * 8) * HW;

    const uint32_t sA = smem_u32(&As[0][0]);
    const uint32_t sB = smem_u32(&Bs[0][0]);
    const __half* wsrc0 = g_wh + (size_t)n0 * CIN;

    // B cp.async mapping (1.5 packets of 16B per thread per stage)
    const int bn_ = tid >> 2, bk_ = tid & 3;
    const int idx2 = tid + 256, bn2 = idx2 >> 2, bk2 = idx2 & 3;

    // ldmatrix per-thread offsets within a stage
    const uint32_t offA = (uint32_t)(lane & 15) * 80u + (uint32_t)(lane >> 4) * 16u
                        + (uint32_t)(wm * 32) * 80u;
    const uint32_t offB01 = (uint32_t)(wn * 24 + ((lane >> 4) << 3) + (lane & 7)) * 80u
                          + (uint32_t)((lane >> 3) & 1) * 16u;
    const int l15 = lane & 15;
    const uint32_t offB2 = (uint32_t)(wn * 24 + 16 + (l15 & 7)) * 80u
                         + (uint32_t)(l15 >> 3) * 16u;

    float acc[2][3][4] = {};
    float ar[2][8];      // A reg pipeline: ar[c%2] holds chunk c

    // ---- prologue ----
    // B chunks 0 and 1 -> stages 0,1 (one commit group each)
    #pragma unroll
    for (int c = 0; c < 2; c++) {
        const __half* ws = wsrc0 + (size_t)c * BK;
        const uint32_t bb = sB + c * B_STAGE;
        cp16(bb + bn_ * 80 + bk_ * 16, ws + (size_t)bn_ * CIN + bk_ * 8);
        if (tid < 128)
            cp16(bb + bn2 * 80 + bk2 * 16, ws + (size_t)bn2 * CIN + bk2 * 8);
        asm volatile("cp.async.commit_group;");
    }
    // A chunk 0 regs
    #pragma unroll
    for (int j = 0; j < 8; j++) ar[0][j] = __ldg(xp + (size_t)j * HW);
    // BN affine table (fused)
    for (int c = tid; c < CIN; c += NTH) {
        float inv = rsqrtf(var[c] + EPS_BN);
        float s = gamma[c] * inv;
        bns[c] = make_float2(s, fmaf(-mean[c], s, beta[c]));
    }
    __syncthreads();                                    // bns visible
    // STS A chunk 0 -> A stage 0
    {
        const int k0 = kq * 8;
        __half h[8];
        #pragma unroll
        for (int j = 0; j < 8; j++) {
            float2 s = bns[k0 + j];
            h[j] = __float2half_rn(fmaxf(fmaf(ar[0][j], s.x, s.y), 0.f));
        }
        *(uint4*)&As[0][am * AST + kq * 8] = *(uint4*)h;
    }
    // A chunk 1 regs
    #pragma unroll
    for (int j = 0; j < 8; j++) ar[1][j] = __ldg(xp + (size_t)(BK + j) * HW);

    // ---- main loop ----
    // iter t: wait B(t); sync; LDG A(t+2); cp.async B(t+2); compute(t); STS A(t+1)
    #pragma unroll 1
    for (int t = 0; t < CHUNKS; t++) {
        asm volatile("cp.async.wait_group 1;");  // B chunk t complete
        __syncthreads();                         // A(t) STS + B(t) visible to all

        if (t + 2 < CHUNKS) {
            const float* xp2 = xp + (size_t)(t + 2) * BK * HW;
            #pragma unroll
            for (int j = 0; j < 8; j++) ar[t & 1][j] = __ldg(xp2 + (size_t)j * HW);
            const __half* ws = wsrc0 + (size_t)(t + 2) * BK;
            const uint32_t bb = sB + ((t + 2) % 3) * B_STAGE;
            cp16(bb + bn_ * 80 + bk_ * 16, ws + (size_t)bn_ * CIN + bk_ * 8);
            if (tid < 128)
                cp16(bb + bn2 * 80 + bk2 * 16, ws + (size_t)bn2 * CIN + bk2 * 8);
        }
        asm volatile("cp.async.commit_group;");  // (possibly empty) keeps count uniform

        // compute chunk t
        const uint32_t aBase = sA + (t & 1) * A_STAGE;
        const uint32_t bBase = sB + (t % 3) * B_STAGE;
        #pragma unroll
        for (int s = 0; s < 2; s++) {
            uint32_t a[2][4], b01[4], b2[2];
            ldm_x4(a[0], aBase + offA + s * 32);
            ldm_x4(a[1], aBase + offA + 16 * 80 + s * 32);
            ldm_x4(b01, bBase + offB01 + s * 32);
            ldm_x2(b2,  bBase + offB2  + s * 32);
            const uint32_t* bf[3] = { &b01[0], &b01[2], &b2[0] };
            #pragma unroll
            for (int mi = 0; mi < 2; mi++)
                #pragma unroll
                for (int ni = 0; ni < 3; ni++) {
                    asm volatile(
                        "mma.sync.aligned.m16n8k16.row.col.f32.f16.f16.f32 "
                        "{%0,%1,%2,%3},{%4,%5,%6,%7},{%8,%9},{%0,%1,%2,%3};"
                        : "+f"(acc[mi][ni][0]), "+f"(acc[mi][ni][1]),
                          "+f"(acc[mi][ni][2]), "+f"(acc[mi][ni][3])
                        : "r"(a[mi][0]), "r"(a[mi][1]), "r"(a[mi][2]), "r"(a[mi][3]),
                          "r"(bf[ni][0]), "r"(bf[ni][1]));
                }
        }

        // STS A chunk t+1 from reg buffer (written into the stage just consumed... no:
        // stage (t+1)&1, consumed stage is (t)&1 — disjoint; WAR on (t+1)&1 was chunk t-1,
        // consumed last iter, ordered by this iter's barrier)
        if (t + 1 < CHUNKS) {
            const int k0 = (t + 1) * BK + kq * 8;
            __half h[8];
            #pragma unroll
            for (int j = 0; j < 8; j++) {
                float2 s = bns[k0 + j];
                h[j] = __float2half_rn(fmaxf(fmaf(ar[(t + 1) & 1][j], s.x, s.y), 0.f));
            }
            *(uint4*)&As[(t + 1) & 1][am * AST + kq * 8] = *(uint4*)h;
        }
    }

    // ---- epilogue: out[b][n][hw] ----
    #pragma unroll
    for (int mi = 0; mi < 2; mi++) {
        #pragma unroll
        for (int hh = 0; hh < 2; hh++) {
            const int m = m0 + wm * 32 + mi * 16 + g + hh * 8;
            float* ob = out + (size_t)(m / HW) * ((size_t)COUT * HW) + (m % HW);
            #pragma unroll
            for (int ni = 0; ni < 3; ni++) {
                const int cc = n0 + wn * 24 + ni * 8 + tq * 2;
                ob[(size_t)cc * HW]       = acc[mi][ni][hh * 2 + 0];
                ob[(size_t)(cc + 1) * HW] = acc[mi][ni][hh * 2 + 1];
            }
        }
    }
}

extern "C" void kernel_launch(void* const* d_in, const int* in_sizes, int n_in,
                              void* d_out, int out_size) {
    const float* x     = (const float*)d_in[0];
    const float* gamma = (const float*)d_in[1];
    const float* beta  = (const float*)d_in[2];
    const float* mean  = (const float*)d_in[3];
    const float* var   = (const float*)d_in[4];
    const float* W     = (const float*)d_in[5];
    float* out = (float*)d_out;

    prep_w_k<<<(COUT * CIN + 255) / 256, 256>>>(W);
    gemm_k<<<(M_TOTAL / BM) * 2, NTH>>>(x, gamma, beta, mean, var, out);
}

// round 7
// speedup vs baseline: 1.2240x; 1.2240x over previous
#include <cuda_runtime.h>
#include <cuda_fp16.h>
#include <cstdint>

// ---------------- problem constants ----------------
#define CIN     2112
#define COUT    192
#define HW      49
#define M_TOTAL 12544          // 256*49
#define BM      64
#define BN      96
#define BK      64
#define CHUNKS  33             // 2112/64
#define NTH     256
#define EPS_BN  1e-5f

// smem row stride: 64 k halfs (128B) + 16B pad = 144B (16B-aligned for ldmatrix!)
#define RSTB    144
#define A_STAGE (BM * RSTB)      // 9216 B
#define B_STAGE (BN * RSTB)      // 13824 B
#define SMEM_TOTAL ((A_STAGE + B_STAGE) * 3)  // 69120 B

// ---------------- persistent scratch ----------------
__device__ __half g_wh[COUT * CIN];                    // W fp16, k-major
__device__ __half g_ah[(size_t)M_TOTAL * CIN];         // relu(bn(x)) fp16, k-major (~53MB)

__global__ void prep_w_k(const float* __restrict__ W) {
    int i = blockIdx.x * blockDim.x + threadIdx.x;
    if (i < COUT * CIN) g_wh[i] = __float2half_rn(W[i]);
}

// BN+ReLU+fp16+transpose: x[b][k][hw] -> g_ah[b*49+hw][k]
__global__ __launch_bounds__(NTH)
void prep_x_k(const float* __restrict__ x,
              const float* __restrict__ gamma, const float* __restrict__ beta,
              const float* __restrict__ mean,  const float* __restrict__ var) {
    __shared__ __half sm[32][52];
    const int kt = blockIdx.x;        // 0..65
    const int b  = blockIdx.y;        // 0..255
    const int tid = threadIdx.x;
    const int k0 = kt * 32;

    // load phase: thread -> (k-row r, 7 hw cols)
    {
        const int r = tid >> 3;
        const int c0 = (tid & 7) * 7;
        const int k = k0 + r;
        const float inv = rsqrtf(var[k] + EPS_BN);
        const float s = gamma[k] * inv;
        const float t = fmaf(-mean[k], s, beta[k]);
        const float* xr = x + ((size_t)b * CIN + k) * HW;
        #pragma unroll
        for (int j = 0; j < 7; j++) {
            const int c = c0 + j;
            if (c < HW)
                sm[r][c] = __float2half_rn(fmaxf(fmaf(xr[c], s, t), 0.f));
        }
    }
    __syncthreads();
    // store phase: thread -> (hw col c, 8-k packet p); 49*4 = 196 threads
    if (tid < HW * 4) {
        const int c = tid >> 2, p = tid & 3;
        uint32_t w[4];
        #pragma unroll
        for (int i = 0; i < 4; i++) {
            const int r = p * 8 + i * 2;
            w[i] = (uint32_t)__half_as_ushort(sm[r][c])
                 | ((uint32_t)__half_as_ushort(sm[r + 1][c]) << 16);
        }
        uint4 v = make_uint4(w[0], w[1], w[2], w[3]);
        *(uint4*)(g_ah + ((size_t)b * HW + c) * CIN + k0 + p * 8) = v;
    }
}

// ---------------- helpers ----------------
__device__ __forceinline__ uint32_t smem_u32(const void* p) {
    uint32_t a;
    asm("{ .reg .u64 t; cvta.to.shared.u64 t, %1; cvt.u32.u64 %0, t; }" : "=r"(a) : "l"(p));
    return a;
}
__device__ __forceinline__ void cp16(uint32_t dst, const void* src) {
    asm volatile("cp.async.cg.shared.global [%0], [%1], 16;" :: "r"(dst), "l"(src));
}
__device__ __forceinline__ void ldm_x4(uint32_t* r, uint32_t addr) {
    asm volatile("ldmatrix.sync.aligned.m8n8.x4.shared.b16 {%0,%1,%2,%3}, [%4];"
                 : "=r"(r[0]), "=r"(r[1]), "=r"(r[2]), "=r"(r[3]) : "r"(addr));
}
__device__ __forceinline__ void ldm_x2(uint32_t* r, uint32_t addr) {
    asm volatile("ldmatrix.sync.aligned.m8n8.x2.shared.b16 {%0,%1}, [%2];"
                 : "=r"(r[0]), "=r"(r[1]) : "r"(addr));
}

// ---------------- pure fp16 GEMM ----------------
// C[M, N=192] = g_ah[M, K] * g_wh[N, K]^T ; grid: 196 m-tiles x 2 n-halves
__global__ __launch_bounds__(NTH, 3)
void gemm_k(float* __restrict__ out) {
    extern __shared__ char smem[];
    const uint32_t sA = smem_u32(smem);                     // 3 A stages
    const uint32_t sB = sA + 3 * A_STAGE;                   // 3 B stages

    const int tid  = threadIdx.x;
    const int lane = tid & 31, warp = tid >> 5;
    const int wm = warp & 1, wn = warp >> 1;                // 2 x 4 warp grid
    const int g  = lane >> 2, tq = lane & 3;

    const int m0 = (blockIdx.x >> 1) * BM;
    const int n0 = (blockIdx.x & 1) * BN;

    const __half* asrc = g_ah + (size_t)m0 * CIN;
    const __half* bsrc = g_wh + (size_t)n0 * CIN;

    // ldmatrix per-thread offsets within a stage (row stride 144B, 16B aligned)
    const uint32_t offA = (uint32_t)(wm * 32 + (lane & 15)) * RSTB + (uint32_t)(lane >> 4) * 16u;
    const uint32_t offB01 = (uint32_t)(wn * 24 + ((lane >> 4) << 3) + (lane & 7)) * RSTB
                          + (uint32_t)((lane >> 3) & 1) * 16u;
    const int l15 = lane & 15;
    const uint32_t offB2 = (uint32_t)(wn * 24 + 16 + (l15 & 7)) * RSTB
                         + (uint32_t)(l15 >> 3) * 16u;

    float acc[2][3][4] = {};

    // ---- issue one chunk's cp.async (A: 512 packets, B: 768 packets) ----
    auto issue = [&](int c) {
        const uint32_t aBase = sA + (c % 3) * A_STAGE;
        const uint32_t bBase = sB + (c % 3) * B_STAGE;
        const __half* aw = asrc + c * BK;
        const __half* bw = bsrc + c * BK;
        #pragma unroll
        for (int i = 0; i < 2; i++) {
            const int q = tid + i * NTH, r = q >> 3, p = q & 7;
            cp16(aBase + r * RSTB + p * 16, aw + (size_t)r * CIN + p * 8);
        }
        #pragma unroll
        for (int i = 0; i < 3; i++) {
            const int q = tid + i * NTH, r = q >> 3, p = q & 7;
            cp16(bBase + r * RSTB + p * 16, bw + (size_t)r * CIN + p * 8);
        }
    };

    // ---- prologue: chunks 0,1 ----
    issue(0);
    asm volatile("cp.async.commit_group;");
    issue(1);
    asm volatile("cp.async.commit_group;");

    // ---- main loop ----
    #pragma unroll 1
    for (int t = 0; t < CHUNKS; t++) {
        asm volatile("cp.async.wait_group 1;");     // chunk t resident
        __syncthreads();                            // visibility + WAR on stage (t+2)%3

        if (t + 2 < CHUNKS) issue(t + 2);
        asm volatile("cp.async.commit_group;");     // (possibly empty) uniform count

        const uint32_t aBase = sA + (t % 3) * A_STAGE;
        const uint32_t bBase = sB + (t % 3) * B_STAGE;
        #pragma unroll
        for (int s = 0; s < 4; s++) {
            uint32_t a[2][4], b01[4], b2[2];
            ldm_x4(a[0], aBase + offA + s * 32);
            ldm_x4(a[1], aBase + offA + 16 * RSTB + s * 32);
            ldm_x4(b01, bBase + offB01 + s * 32);
            ldm_x2(b2,  bBase + offB2  + s * 32);
            const uint32_t* bf[3] = { &b01[0], &b01[2], &b2[0] };
            #pragma unroll
            for (int mi = 0; mi < 2; mi++)
                #pragma unroll
                for (int ni = 0; ni < 3; ni++) {
                    asm volatile(
                        "mma.sync.aligned.m16n8k16.row.col.f32.f16.f16.f32 "
                        "{%0,%1,%2,%3},{%4,%5,%6,%7},{%8,%9},{%0,%1,%2,%3};"
                        : "+f"(acc[mi][ni][0]), "+f"(acc[mi][ni][1]),
                          "+f"(acc[mi][ni][2]), "+f"(acc[mi][ni][3])
                        : "r"(a[mi][0]), "r"(a[mi][1]), "r"(a[mi][2]), "r"(a[mi][3]),
                          "r"(bf[ni][0]), "r"(bf[ni][1]));
                }
        }
    }

    // ---- epilogue: out[b][n][hw] ----
    #pragma unroll
    for (int mi = 0; mi < 2; mi++) {
        #pragma unroll
        for (int hh = 0; hh < 2; hh++) {
            const int m = m0 + wm * 32 + mi * 16 + g + hh * 8;
            float* ob = out + (size_t)(m / HW) * ((size_t)COUT * HW) + (m % HW);
            #pragma unroll
            for (int ni = 0; ni < 3; ni++) {
                const int cc = n0 + wn * 24 + ni * 8 + tq * 2;
                ob[(size_t)cc * HW]       = acc[mi][ni][hh * 2 + 0];
                ob[(size_t)(cc + 1) * HW] = acc[mi][ni][hh * 2 + 1];
            }
        }
    }
}

extern "C" void kernel_launch(void* const* d_in, const int* in_sizes, int n_in,
                              void* d_out, int out_size) {
    const float* x     = (const float*)d_in[0];
    const float* gamma = (const float*)d_in[1];
    const float* beta  = (const float*)d_in[2];
    const float* mean  = (const float*)d_in[3];
    const float* var   = (const float*)d_in[4];
    const float* W     = (const float*)d_in[5];
    float* out = (float*)d_out;

    prep_w_k<<<(COUT * CIN + 255) / 256, 256>>>(W);
    prep_x_k<<<dim3(CIN / 32, 256), NTH>>>(x, gamma, beta, mean, var);
    cudaFuncSetAttribute(gemm_k, cudaFuncAttributeMaxDynamicSharedMemorySize, SMEM_TOTAL);
    gemm_k<<<(M_TOTAL / BM) * 2, NTH, SMEM_TOTAL>>>(out);
}

// round 9
// speedup vs baseline: 1.4027x; 1.1460x over previous
#include <cuda_runtime.h>
#include <cuda_fp16.h>
#include <cstdint>

// ---------------- problem constants ----------------
#define CIN     2112
#define COUT    192
#define HW      49
#define M_TOTAL 12544          // 256*49
#define BM      64
#define BN      96
#define BK      64
#define CHUNKS  33             // 2112/64
#define NTH     256
#define EPS_BN  1e-5f

// smem: row stride 144B (64 halfs + 16B pad; 16B-aligned for ldmatrix)
#define RSTB    144
#define A_STAGE (BM * RSTB)            // 9216 B
#define B_STAGE (BN * RSTB)            // 13824 B
#define SM_BNS  0                      // float2[2112] = 16896 B
#define SM_A    16896                  // 2 stages
#define SM_B    (SM_A + 2 * A_STAGE)   // 35328, 2 stages
#define SMEM_TOTAL (SM_B + 2 * B_STAGE)  // 62976 B
// epilogue C staging reuses [SM_A ...): 96 rows x 66 floats = 25344 B
#define CST     66

// ---------------- persistent scratch ----------------
__device__ __half g_wh[COUT * CIN];    // W fp16, k-major

__global__ void prep_w_k(const float* __restrict__ W) {
    int i = blockIdx.x * blockDim.x + threadIdx.x;
    if (i < COUT * CIN) g_wh[i] = __float2half_rn(W[i]);
}

// ---------------- helpers ----------------
__device__ __forceinline__ uint32_t smem_u32(const void* p) {
    uint32_t a;
    asm("{ .reg .u64 t; cvta.to.shared.u64 t, %1; cvt.u32.u64 %0, t; }" : "=r"(a) : "l"(p));
    return a;
}
__device__ __forceinline__ void cp16(uint32_t dst, const void* src) {
    asm volatile("cp.async.cg.shared.global [%0], [%1], 16;" :: "r"(dst), "l"(src));
}
__device__ __forceinline__ void ldm_x4(uint32_t* r, uint32_t addr) {
    asm volatile("ldmatrix.sync.aligned.m8n8.x4.shared.b16 {%0,%1,%2,%3}, [%4];"
                 : "=r"(r[0]), "=r"(r[1]), "=r"(r[2]), "=r"(r[3]) : "r"(addr));
}
__device__ __forceinline__ void ldm_x2(uint32_t* r, uint32_t addr) {
    asm volatile("ldmatrix.sync.aligned.m8n8.x2.shared.b16 {%0,%1}, [%2];"
                 : "=r"(r[0]), "=r"(r[1]) : "r"(addr));
}

// ---------------- fused BN+ReLU + fp16 GEMM ----------------
// C[M=12544, N=192] = relu(x*s+t)[M, K] * W[N, K]^T ; grid 392 = 196 m x 2 n
__global__ __launch_bounds__(NTH, 3)
void gemm_k(const float* __restrict__ x,
            const float* __restrict__ gamma, const float* __restrict__ beta,
            const float* __restrict__ mean,  const float* __restrict__ var,
            float* __restrict__ out) {
    extern __shared__ char smem[];
    float2* bns = (float2*)(smem + SM_BNS);
    const uint32_t sA = smem_u32(smem) + SM_A;
    const uint32_t sB = smem_u32(smem) + SM_B;

    const int tid  = threadIdx.x;
    const int lane = tid & 31, warp = tid >> 5;
    const int wm = warp & 1, wn = warp >> 1;        // 2 x 4 warp grid
    const int g  = lane >> 2, tq = lane & 3;

    const int m0 = (blockIdx.x >> 1) * BM;
    const int n0 = (blockIdx.x & 1) * BN;

    // A loader: thread -> (m = tid&63, 16 k at kq*16)
    const int am = tid & 63, kq = tid >> 6;
    const int mg = m0 + am;
    const float* xp = x + (size_t)(mg / HW) * ((size_t)CIN * HW) + (mg % HW)
                        + (size_t)(kq * 16) * HW;

    const __half* bsrc = g_wh + (size_t)n0 * CIN;

    // ldmatrix per-thread offsets within a stage
    const uint32_t offA = (uint32_t)(wm * 32 + (lane & 15)) * RSTB + (uint32_t)(lane >> 4) * 16u;
    const uint32_t offB01 = (uint32_t)(wn * 24 + ((lane >> 4) << 3) + (lane & 7)) * RSTB
                          + (uint32_t)((lane >> 3) & 1) * 16u;
    const int l15 = lane & 15;
    const uint32_t offB2 = (uint32_t)(wn * 24 + 16 + (l15 & 7)) * RSTB
                         + (uint32_t)(l15 >> 3) * 16u;

    float acc[2][3][4] = {};
    float ar[16];

    // B cp.async for one chunk: 96 rows x 8 packets = 768 = 3 x 256
    auto issueB = [&](int c, uint32_t bb) {
        const __half* bw = bsrc + (size_t)c * BK;
        #pragma unroll
        for (int i = 0; i < 3; i++) {
            const int q = tid + i * NTH, r = q >> 3, p = q & 7;
            cp16(bb + r * RSTB + p * 16, bw + (size_t)r * CIN + p * 8);
        }
    };

    // ---- prologue ----
    issueB(0, sB);
    asm volatile("cp.async.commit_group;");
    #pragma unroll
    for (int j = 0; j < 16; j++) ar[j] = __ldg(xp + (size_t)j * HW);
    for (int c = tid; c < CIN; c += NTH) {
        float inv = rsqrtf(var[c] + EPS_BN);
        float s = gamma[c] * inv;
        bns[c] = make_float2(s, fmaf(-mean[c], s, beta[c]));
    }
    __syncthreads();                                 // bns ready
    {   // STS A chunk 0 -> stage 0
        const int k0 = kq * 16;
        __half h[16];
        #pragma unroll
        for (int j = 0; j < 16; j++) {
            float2 s = bns[k0 + j];
            h[j] = __float2half_rn(fmaxf(fmaf(ar[j], s.x, s.y), 0.f));
        }
        *(uint4*)(smem + SM_A + am * RSTB + kq * 32)      = *(uint4*)&h[0];
        *(uint4*)(smem + SM_A + am * RSTB + kq * 32 + 16) = *(uint4*)&h[8];
    }
    asm volatile("cp.async.wait_group 0;");
    __syncthreads();

    // ---- main loop: iter t: LDG A(t+1); cp B(t+1); compute(t); STS A(t+1); wait; sync
    #pragma unroll 1
    for (int t = 0; t < CHUNKS; t++) {
        const int cur = t & 1, nxt = cur ^ 1;
        const bool more = (t + 1 < CHUNKS);

        if (more) {
            const float* xp2 = xp + (size_t)(t + 1) * BK * HW;
            #pragma unroll
            for (int j = 0; j < 16; j++) ar[j] = __ldg(xp2 + (size_t)j * HW);
            issueB(t + 1, sB + nxt * B_STAGE);
        }
        asm volatile("cp.async.commit_group;");

        // compute chunk t: 4 k16 steps
        const uint32_t aBase = sA + cur * A_STAGE;
        const uint32_t bBase = sB + cur * B_STAGE;
        #pragma unroll
        for (int s = 0; s < 4; s++) {
            uint32_t a[2][4], b01[4], b2[2];
            ldm_x4(a[0], aBase + offA + s * 32);
            ldm_x4(a[1], aBase + offA + 16 * RSTB + s * 32);
            ldm_x4(b01, bBase + offB01 + s * 32);
            ldm_x2(b2,  bBase + offB2  + s * 32);
            const uint32_t* bf[3] = { &b01[0], &b01[2], &b2[0] };
            #pragma unroll
            for (int mi = 0; mi < 2; mi++)
                #pragma unroll
                for (int ni = 0; ni < 3; ni++) {
                    asm volatile(
                        "mma.sync.aligned.m16n8k16.row.col.f32.f16.f16.f32 "
                        "{%0,%1,%2,%3},{%4,%5,%6,%7},{%8,%9},{%0,%1,%2,%3};"
                        : "+f"(acc[mi][ni][0]), "+f"(acc[mi][ni][1]),
                          "+f"(acc[mi][ni][2]), "+f"(acc[mi][ni][3])
                        : "r"(a[mi][0]), "r"(a[mi][1]), "r"(a[mi][2]), "r"(a[mi][3]),
                          "r"(bf[ni][0]), "r"(bf[ni][1]));
                }
        }

        if (more) {
            const int k0 = (t + 1) * BK + kq * 16;
            __half h[16];
            #pragma unroll
            for (int j = 0; j < 16; j++) {
                float2 s = bns[k0 + j];
                h[j] = __float2half_rn(fmaxf(fmaf(ar[j], s.x, s.y), 0.f));
            }
            char* ab = smem + SM_A + nxt * A_STAGE + am * RSTB + kq * 32;
            *(uint4*)(ab)      = *(uint4*)&h[0];
            *(uint4*)(ab + 16) = *(uint4*)&h[8];
        }
        asm volatile("cp.async.wait_group 0;");
        __syncthreads();
    }

    // ---- epilogue: acc -> Cs[n][m] in smem -> coalesced STG ----
    float* Cs = (float*)(smem + SM_A);   // 96 x 66 floats (reuses pipeline smem)
    #pragma unroll
    for (int mi = 0; mi < 2; mi++)
        #pragma unroll
        for (int hh = 0; hh < 2; hh++) {
            const int mloc = wm * 32 + mi * 16 + g + hh * 8;
            #pragma unroll
            for (int ni = 0; ni < 3; ni++) {
                const int nloc = wn * 24 + ni * 8 + tq * 2;
                Cs[nloc * CST + mloc]       = acc[mi][ni][hh * 2 + 0];
                Cs[(nloc + 1) * CST + mloc] = acc[mi][ni][hh * 2 + 1];
            }
        }
    __syncthreads();

    // each warp writes 12 n-rows; lane covers m = 2*lane, 2*lane+1 (hw-contiguous)
    {
        const int mg0 = m0 + lane * 2;
        const int b0_ = mg0 / HW,        hw0 = mg0 - b0_ * HW;
        const int b1_ = (mg0 + 1) / HW,  hw1 = (mg0 + 1) - b1_ * HW;
        #pragma unroll
        for (int r = 0; r < 12; r++) {
            const int nn = n0 + warp * 12 + r;
            const float2 v = *(const float2*)&Cs[(warp * 12 + r) * CST + lane * 2];
            out[((size_t)b0_ * COUT + nn) * HW + hw0] = v.x;
            out[((size_t)b1_ * COUT + nn) * HW + hw1] = v.y;
        }
    }
}

extern "C" void kernel_launch(void* const* d_in, const int* in_sizes, int n_in,
                              void* d_out, int out_size) {
    const float* x     = (const float*)d_in[0];
    const float* gamma = (const float*)d_in[1];
    const float* beta  = (const float*)d_in[2];
    const float* mean  = (const float*)d_in[3];
    const float* var   = (const float*)d_in[4];
    const float* W     = (const float*)d_in[5];
    float* out = (float*)d_out;

    prep_w_k<<<(COUT * CIN + 255) / 256, 256>>>(W);
    cudaFuncSetAttribute(gemm_k, cudaFuncAttributeMaxDynamicSharedMemorySize, SMEM_TOTAL);
    gemm_k<<<(M_TOTAL / BM) * 2, NTH, SMEM_TOTAL>>>(x, gamma, beta, mean, var, out);
}